// round 16
// baseline (speedup 1.0000x reference)
#include <cuda_runtime.h>
#include <cuda_fp16.h>
#include <math.h>
#include <stdint.h>

// Problem constants
#define NN    30000
#define NE    480000
#define HD    256
#define MPAD  30080      // 235*128
#define KTOT  768        // x_aug | h | t1
#define NCOL  1024       // 4 gates * 256 (gate-blocked: col = g*256 + j)
#define NH    (NN * HD)

// ---------------- static device scratch ----------------
__device__ float g_deg[NN];
__device__ int   g_cnt_src[NN], g_cnt_dst[NN];
__device__ int   g_off_src[NN], g_off_dst[NN];
__device__ int   g_cur_src[NN], g_cur_dst[NN];
__device__ int   g_nbr_src[NE];                   // resolved: snid[e] bucketed by src
__device__ int   g_nbr_dst[NE];                   // resolved: dnid[e] bucketed by dst
__device__ int   g_hsrc[NE];                      // resolved: src[e]  bucketed by dst
__device__ float g_nrm[NE];                       // resolved: norm_e  bucketed by dst
__device__ float g_Z[MPAD * NCOL];                // gate pre-activations (fp32)
__device__ __align__(16) __half g_Ah[MPAD * KTOT];   // A hi (fp16); pad rows stay 0
__device__ __align__(16) __half g_Al[MPAD * KTOT];   // A lo (fp16)
__device__ __align__(16) __half g_W [NCOL * KTOT];   // W transposed [n][k], single fp16
__device__ __align__(16) __half g_Rh[MPAD * HD];     // relu(h0) hi
__device__ __align__(16) __half g_Rl[MPAD * HD];     // relu(h0) lo
__device__ __align__(16) __half g_WlT[HD * HD];      // W_lin transposed, single fp16

__device__ __forceinline__ float sigf(float x) { return 1.0f / (1.0f + __expf(-x)); }
__device__ __forceinline__ float tanhfast(float x) {
    return 2.0f / (1.0f + __expf(-2.0f * x)) - 1.0f;
}

__device__ __forceinline__ uint32_t smem_u32(const void* p) {
    uint32_t a;
    asm("{ .reg .u64 t; cvta.to.shared.u64 t, %1; cvt.u32.u64 %0, t; }" : "=r"(a) : "l"(p));
    return a;
}

// ---------------- CSR build ----------------
__global__ __launch_bounds__(256) void k_zero() {
    int i = blockIdx.x * blockDim.x + threadIdx.x;
    if (i < NN) { g_cnt_src[i] = 0; g_cnt_dst[i] = 0; g_deg[i] = 0.f; }
}

__global__ __launch_bounds__(256) void k_count(const int* __restrict__ src,
                                               const int* __restrict__ dst,
                                               const float* __restrict__ ew) {
    int e = blockIdx.x * blockDim.x + threadIdx.x;
    if (e < NE) {
        int s = src[e], d = dst[e];
        atomicAdd(&g_cnt_src[s], 1);
        atomicAdd(&g_cnt_dst[d], 1);
        atomicAdd(&g_deg[s], ew[e]);
    }
}

__global__ __launch_bounds__(256) void k_dinv() {
    int i = blockIdx.x * blockDim.x + threadIdx.x;
    if (i < NN) {
        float d = g_deg[i];
        g_deg[i] = (d > 0.f) ? rsqrtf(fmaxf(d, 1e-12f)) : 0.f;
    }
}

#define SCH 30   // 1024*30 = 30720 >= NN
__global__ __launch_bounds__(1024) void k_scan() {
    __shared__ int sh[1024];
    int t = threadIdx.x;
    int base = t * SCH;
#pragma unroll 1
    for (int pass = 0; pass < 2; pass++) {
        const int* cnt = pass ? g_cnt_dst : g_cnt_src;
        int* off = pass ? g_off_dst : g_off_src;
        int* cur = pass ? g_cur_dst : g_cur_src;
        int local = 0;
        for (int i = 0; i < SCH; i++) {
            int idx = base + i;
            if (idx < NN) local += cnt[idx];
        }
        sh[t] = local;
        __syncthreads();
        for (int o = 1; o < 1024; o <<= 1) {
            int v = 0;
            if (t >= o) v = sh[t - o];
            __syncthreads();
            if (t >= o) sh[t] += v;
            __syncthreads();
        }
        int run = (t > 0) ? sh[t - 1] : 0;
        for (int i = 0; i < SCH; i++) {
            int idx = base + i;
            if (idx < NN) {
                off[idx] = run;
                cur[idx] = run;
                run += cnt[idx];
            }
        }
        __syncthreads();
    }
}

__global__ __launch_bounds__(256) void k_fill(const int* __restrict__ src,
                                              const int* __restrict__ dst,
                                              const int* __restrict__ snid,
                                              const int* __restrict__ dnid,
                                              const float* __restrict__ ew) {
    int e = blockIdx.x * blockDim.x + threadIdx.x;
    if (e < NE) {
        int s = src[e], d = dst[e];
        int ps = atomicAdd(&g_cur_src[s], 1);
        g_nbr_src[ps] = snid[e];
        int pd = atomicAdd(&g_cur_dst[d], 1);
        g_nbr_dst[pd] = dnid[e];
        g_hsrc[pd] = s;
        g_nrm[pd] = -g_deg[s] * ew[e] * g_deg[d];
    }
}

// ---------------- fp32 -> fp16 hi/lo split ----------------
__device__ __forceinline__ void split4h(float4 v, uint2& hi, uint2& lo) {
    __half h[4], l[4];
    float f[4] = {v.x, v.y, v.z, v.w};
#pragma unroll
    for (int t = 0; t < 4; t++) {
        h[t] = __float2half(f[t]);
        l[t] = __float2half(f[t] - __half2float(h[t]));
    }
    hi = *reinterpret_cast<uint2*>(h);
    lo = *reinterpret_cast<uint2*>(l);
}

// ---------------- gather + pack A (fp16 split), plain broadcast-index form ----
__global__ __launch_bounds__(256) void k_gatherA(
    const float* __restrict__ x, const float* __restrict__ h)
{
    int node = blockIdx.x * 4 + (threadIdx.x >> 6);
    int t = threadIdx.x & 63;
    if (node >= NN) return;

    const float4* x4 = reinterpret_cast<const float4*>(x);
    const float4* h4 = reinterpret_cast<const float4*>(h);

    float4 ax = x4[(size_t)node * 64 + t];
    float4 at = make_float4(0.f, 0.f, 0.f, 0.f);

    {
        int o = g_off_src[node], c = g_cnt_src[node];
#pragma unroll 8
        for (int i = 0; i < c; i++) {
            int sn = g_nbr_src[o + i];
            float4 v = x4[(size_t)sn * 64 + t];
            ax.x += v.x; ax.y += v.y; ax.z += v.z; ax.w += v.w;
        }
    }
    {
        int o = g_off_dst[node], c = g_cnt_dst[node];
#pragma unroll 8
        for (int i = 0; i < c; i++) {
            int dn = g_nbr_dst[o + i];
            int s  = g_hsrc[o + i];
            float nm = g_nrm[o + i];
            float4 v = x4[(size_t)dn * 64 + t];
            ax.x += v.x; ax.y += v.y; ax.z += v.z; ax.w += v.w;
            float4 hv = h4[(size_t)s * 64 + t];
            at.x += nm * hv.x; at.y += nm * hv.y; at.z += nm * hv.z; at.w += nm * hv.w;
        }
    }

    float4 hr = h4[(size_t)node * 64 + t];

    uint2 hi, lo;
    size_t rb = (size_t)node * KTOT;
    split4h(ax, hi, lo);
    *reinterpret_cast<uint2*>(g_Ah + rb + t * 4) = hi;
    *reinterpret_cast<uint2*>(g_Al + rb + t * 4) = lo;
    split4h(hr, hi, lo);
    *reinterpret_cast<uint2*>(g_Ah + rb + 256 + t * 4) = hi;
    *reinterpret_cast<uint2*>(g_Al + rb + 256 + t * 4) = lo;
    split4h(at, hi, lo);
    *reinterpret_cast<uint2*>(g_Ah + rb + 512 + t * 4) = hi;
    *reinterpret_cast<uint2*>(g_Al + rb + 512 + t * 4) = lo;
}

// ---------------- weight packs (single fp16) ----------------
__global__ __launch_bounds__(256) void k_conv_W(
    const float* __restrict__ Wi, const float* __restrict__ Wf,
    const float* __restrict__ Wg, const float* __restrict__ Wo,
    const float* __restrict__ Wci, const float* __restrict__ Wcf,
    const float* __restrict__ Wcg, const float* __restrict__ Wco)
{
    int i = blockIdx.x * blockDim.x + threadIdx.x;   // over NCOL*96
    if (i >= NCOL * 96) return;
    int n = i / 96;
    int kc = i % 96;
    int g = n >> 8, j = n & 255;
    const float* Win[4] = {Wi, Wf, Wg, Wo};
    const float* Wc[4]  = {Wci, Wcf, Wcg, Wco};
    __half v[8];
#pragma unroll
    for (int t = 0; t < 8; t++) {
        int k = kc * 8 + t;
        float f;
        if (k < 256)      f = Win[g][k * 256 + j];
        else if (k < 512) f = Wc[g][(k - 256) * 256 + j];
        else              f = Wc[g][65536 + (k - 512) * 256 + j];
        v[t] = __float2half(f);
    }
    reinterpret_cast<uint4*>(g_W)[i] = *reinterpret_cast<uint4*>(v);
}

__global__ __launch_bounds__(256) void k_conv_Wlin(const float* __restrict__ Wlin) {
    int i = blockIdx.x * blockDim.x + threadIdx.x;   // over 256*32
    if (i >= HD * 32) return;
    int n = i / 32;
    int kc = i % 32;
    __half v[8];
#pragma unroll
    for (int t = 0; t < 8; t++) v[t] = __float2half(Wlin[(kc * 8 + t) * 256 + n]);
    reinterpret_cast<uint4*>(g_WlT)[i] = *reinterpret_cast<uint4*>(v);
}

// ============ fp16 2-product GEMM via mma.sync ============
// C = (Ah + Al)[M x K] @ B^T, B stored [Ncols x K] row-major fp16.
// CTA tile 128x256, 512 threads (16 warps, 2x8), warp tile 64x32,
// K-tile 64, 2-stage cp.async pipeline with issue-before-compute.
#define BKG   64
#define NSTG  2
#define TSTR  144                   // 128B payload + 16B pad; 8-row shifts distinct -> conflict-free
#define A_TILEB (128 * TSTR)        // 18432 B (per A operand)
#define B_TILEB (256 * TSTR)        // 36864 B
#define STAGEB  (2 * A_TILEB + B_TILEB)   // 73728 B
#define SMEM_GEMM (NSTG * STAGEB)   // 147456 B
#define NTHR  512

__device__ __forceinline__ void cp16(uint32_t saddr, const void* gaddr) {
    asm volatile("cp.async.cg.shared.global [%0], [%1], 16;" :: "r"(saddr), "l"(gaddr));
}
__device__ __forceinline__ void ldm_x4(uint32_t* r, uint32_t a) {
    asm volatile("ldmatrix.sync.aligned.m8n8.x4.shared.b16 {%0,%1,%2,%3}, [%4];"
                 : "=r"(r[0]), "=r"(r[1]), "=r"(r[2]), "=r"(r[3]) : "r"(a));
}
__device__ __forceinline__ void mma16816h(float* c, const uint32_t* a, const uint32_t* b) {
    asm volatile(
        "mma.sync.aligned.m16n8k16.row.col.f32.f16.f16.f32 "
        "{%0,%1,%2,%3}, {%4,%5,%6,%7}, {%8,%9}, {%0,%1,%2,%3};"
        : "+f"(c[0]), "+f"(c[1]), "+f"(c[2]), "+f"(c[3])
        : "r"(a[0]), "r"(a[1]), "r"(a[2]), "r"(a[3]), "r"(b[0]), "r"(b[1]));
}

__global__ __launch_bounds__(NTHR) void k_mma(
    const __half* __restrict__ Ah, const __half* __restrict__ Al,
    const __half* __restrict__ B,
    float* __restrict__ C, int K, int Ncols, const float* __restrict__ bias, int m_limit)
{
    extern __shared__ char smem[];
    const int tid = threadIdx.x;
    const int wid = tid >> 5;
    const int lane = tid & 31;
    const int m0 = blockIdx.y * 128;
    const int n0 = blockIdx.x * 256;
    const int nkt = K / BKG;
    const uint32_t sb = smem_u32(smem);

    const int wr = (wid >> 3) * 64;    // 2 row-groups of warps
    const int wc = (wid & 7) * 32;     // 8 col-groups

    // cp.async chunk coords: rows of 128B payload = 8 chunks of 16B per row.
    const int r0 = tid >> 3;           // 0..63
    const int c0 = (tid & 7) * 16;     // byte column within 128B payload

    float acc[4][4][4] = {};

    auto issue_stage = [&](int kt, int buf) {
        uint32_t s = sb + buf * STAGEB;
        const char* ahB = reinterpret_cast<const char*>(Ah);
        const char* alB = reinterpret_cast<const char*>(Al);
        const char* bB  = reinterpret_cast<const char*>(B);
        size_t kb = (size_t)kt * BKG * 2;   // 128 bytes per k-tile
#pragma unroll
        for (int rep = 0; rep < 2; rep++) {         // A rows 0..127
            int row = r0 + rep * 64;
            size_t ga = ((size_t)(m0 + row) * K) * 2 + kb + c0;
            uint32_t so = row * TSTR + c0;
            cp16(s + so, ahB + ga);
            cp16(s + A_TILEB + so, alB + ga);
        }
#pragma unroll
        for (int rep = 0; rep < 4; rep++) {         // B rows 0..255
            int row = r0 + rep * 64;
            size_t gb = ((size_t)(n0 + row) * K) * 2 + kb + c0;
            uint32_t so = row * TSTR + c0;
            cp16(s + 2 * A_TILEB + so, bB + gb);
        }
    };

    // prologue: fill stage 0
    issue_stage(0, 0);
    asm volatile("cp.async.commit_group;");

    for (int kt = 0; kt < nkt; kt++) {
        asm volatile("cp.async.wait_group 0;");
        __syncthreads();                       // all warps done with the buffer we're about to overwrite

        // overlap: issue next stage before computing current
        if (kt + 1 < nkt) issue_stage(kt + 1, (kt + 1) & 1);
        asm volatile("cp.async.commit_group;");

        uint32_t s = sb + (kt & 1) * STAGEB;
        uint32_t sAh = s, sAl = s + A_TILEB, sB = s + 2 * A_TILEB;

#pragma unroll
        for (int ks = 0; ks < 4; ks++) {
            uint32_t ah[4][4], al[4][4], bh[4][2];
            uint32_t aoff = (wr + (lane & 15)) * TSTR + ks * 32 + ((lane >> 4) & 1) * 16;
#pragma unroll
            for (int mt = 0; mt < 4; mt++) {
                ldm_x4(ah[mt], sAh + aoff + mt * 16 * TSTR);
                ldm_x4(al[mt], sAl + aoff + mt * 16 * TSTR);
            }
            // B: one ldmatrix.x4 loads TWO adjacent 8-row N-blocks:
            // matrix i <- addresses from lanes 8i..8i+7.
            // m0: rows (ntp*2+0), k 0-7; m1: rows (ntp*2+0), k 8-15;
            // m2: rows (ntp*2+1), k 0-7; m3: rows (ntp*2+1), k 8-15.
#pragma unroll
            for (int ntp = 0; ntp < 2; ntp++) {
                uint32_t addr = sB +
                    (wc + (ntp * 2 + (lane >> 4)) * 8 + (lane & 7)) * TSTR +
                    ks * 32 + ((lane >> 3) & 1) * 16;
                uint32_t r[4];
                ldm_x4(r, addr);
                bh[ntp * 2][0] = r[0]; bh[ntp * 2][1] = r[1];
                bh[ntp * 2 + 1][0] = r[2]; bh[ntp * 2 + 1][1] = r[3];
            }
#pragma unroll
            for (int mt = 0; mt < 4; mt++)
#pragma unroll
                for (int nt = 0; nt < 4; nt++) {
                    mma16816h(acc[mt][nt], ah[mt], bh[nt]);
                    mma16816h(acc[mt][nt], al[mt], bh[nt]);
                }
        }
    }

#pragma unroll
    for (int mt = 0; mt < 4; mt++) {
        int rAo = m0 + wr + mt * 16 + (lane >> 2);
        int rBo = rAo + 8;
#pragma unroll
        for (int nt = 0; nt < 4; nt++) {
            int col = n0 + wc + nt * 8 + (lane & 3) * 2;
            float bx = 0.f, by = 0.f;
            if (bias) { bx = bias[col]; by = bias[col + 1]; }
            if (rAo < m_limit) {
                float2 v = make_float2(acc[mt][nt][0] + bx, acc[mt][nt][1] + by);
                *reinterpret_cast<float2*>(C + (size_t)rAo * Ncols + col) = v;
            }
            if (rBo < m_limit) {
                float2 v = make_float2(acc[mt][nt][2] + bx, acc[mt][nt][3] + by);
                *reinterpret_cast<float2*>(C + (size_t)rBo * Ncols + col) = v;
            }
        }
    }
}

// ---------------- gates: vectorized x4 — h0, c_new, relu split (fp16) ----------------
__global__ __launch_bounds__(256) void k_gates(
    const float* __restrict__ c,
    const float* __restrict__ bci, const float* __restrict__ bcf,
    const float* __restrict__ bcg, const float* __restrict__ bco,
    const float* __restrict__ bi, const float* __restrict__ bf,
    const float* __restrict__ bg, const float* __restrict__ bo,
    const float* __restrict__ wci, const float* __restrict__ wcf,
    const float* __restrict__ wco,
    float* __restrict__ out)
{
    int i = blockIdx.x * blockDim.x + threadIdx.x;   // over MPAD*64 float4 groups
    if (i >= MPAD * 64) return;
    int row = i >> 6;
    int q = i & 63;
    int j = q * 4;
    size_t off = (size_t)row * HD + j;

    if (row >= NN) {
        uint2 z2 = make_uint2(0u, 0u);
        *reinterpret_cast<uint2*>(g_Rh + off) = z2;
        *reinterpret_cast<uint2*>(g_Rl + off) = z2;
        return;
    }

    const float* zrow = g_Z + (size_t)row * NCOL;
    float4 zi4 = *reinterpret_cast<const float4*>(zrow + j);
    float4 zf4 = *reinterpret_cast<const float4*>(zrow + 256 + j);
    float4 zg4 = *reinterpret_cast<const float4*>(zrow + 512 + j);
    float4 zo4 = *reinterpret_cast<const float4*>(zrow + 768 + j);
    float4 cv4 = *reinterpret_cast<const float4*>(c + off);
    float4 wI = *reinterpret_cast<const float4*>(wci + j);
    float4 wF = *reinterpret_cast<const float4*>(wcf + j);
    float4 wO = *reinterpret_cast<const float4*>(wco + j);

    float zi[4] = {zi4.x, zi4.y, zi4.z, zi4.w};
    float zf[4] = {zf4.x, zf4.y, zf4.z, zf4.w};
    float zg[4] = {zg4.x, zg4.y, zg4.z, zg4.w};
    float zo[4] = {zo4.x, zo4.y, zo4.z, zo4.w};
    float cv[4] = {cv4.x, cv4.y, cv4.z, cv4.w};
    float pI[4] = {wI.x, wI.y, wI.z, wI.w};
    float pF[4] = {wF.x, wF.y, wF.z, wF.w};
    float pO[4] = {wO.x, wO.y, wO.z, wO.w};

    float h0v[4], cnv[4];
    __half rh[4], rl[4];
#pragma unroll
    for (int t = 0; t < 4; t++) {
        float ig = sigf(zi[t] + bci[j + t] + bi[j + t] + pI[t] * cv[t]);
        float fg = sigf(zf[t] + bcf[j + t] + bf[j + t] + pF[t] * cv[t]);
        float gg = tanhfast(zg[t] + bcg[j + t] + bg[j + t]);
        float cn = fg * cv[t] + ig * gg;
        float og = sigf(zo[t] + bco[j + t] + bo[j + t] + pO[t] * cn);
        float h0 = og * tanhfast(cn);
        h0v[t] = h0;
        cnv[t] = cn;
        float r = fmaxf(h0, 0.f);
        rh[t] = __float2half(r);
        rl[t] = __float2half(r - __half2float(rh[t]));
    }
    *reinterpret_cast<float4*>(out + NH + off) = make_float4(h0v[0], h0v[1], h0v[2], h0v[3]);
    *reinterpret_cast<float4*>(out + 2 * NH + off) = make_float4(cnv[0], cnv[1], cnv[2], cnv[3]);
    *reinterpret_cast<uint2*>(g_Rh + off) = *reinterpret_cast<uint2*>(rh);
    *reinterpret_cast<uint2*>(g_Rl + off) = *reinterpret_cast<uint2*>(rl);
}

// ---------------- launch ----------------
extern "C" void kernel_launch(void* const* d_in, const int* in_sizes, int n_in,
                              void* d_out, int out_size) {
    const float* x    = (const float*)d_in[0];
    const int*   ei   = (const int*)d_in[1];
    const float* ew   = (const float*)d_in[2];
    const float* h    = (const float*)d_in[3];
    const float* c    = (const float*)d_in[4];
    const int*   snid = (const int*)d_in[5];
    const int*   dnid = (const int*)d_in[6];
    const float* Wi   = (const float*)d_in[7];
    const float* Wf   = (const float*)d_in[8];
    const float* Wg   = (const float*)d_in[9];
    const float* Wo   = (const float*)d_in[10];
    const float* Wci  = (const float*)d_in[11];
    const float* Wcf  = (const float*)d_in[12];
    const float* Wcg  = (const float*)d_in[13];
    const float* Wco  = (const float*)d_in[14];
    const float* bci  = (const float*)d_in[15];
    const float* bcf  = (const float*)d_in[16];
    const float* bcg  = (const float*)d_in[17];
    const float* bco  = (const float*)d_in[18];

    const float *bi, *bf, *bg, *bo, *blin, *wci, *wcf, *wco, *Wlin;
    if (in_sizes[27] == 65536) {
        bi = (const float*)d_in[19]; bf = (const float*)d_in[20];
        bg = (const float*)d_in[21]; bo = (const float*)d_in[22];
        blin = (const float*)d_in[23];
        wci = (const float*)d_in[24]; wcf = (const float*)d_in[25];
        wco = (const float*)d_in[26];
        Wlin = (const float*)d_in[27];
    } else {
        wci = (const float*)d_in[19]; wcf = (const float*)d_in[20];
        wco = (const float*)d_in[21];
        bi = (const float*)d_in[22]; bf = (const float*)d_in[23];
        bg = (const float*)d_in[24]; bo = (const float*)d_in[25];
        Wlin = (const float*)d_in[26];
        blin = (const float*)d_in[27];
    }

    const int* src = ei;
    const int* dst = ei + NE;
    float* out = (float*)d_out;

    cudaFuncSetAttribute(k_mma, cudaFuncAttributeMaxDynamicSharedMemorySize, SMEM_GEMM);

    // CSR build (field-resolving) + weight packs
    k_zero<<<(NN + 255) / 256, 256>>>();
    k_conv_W<<<(NCOL * 96 + 255) / 256, 256>>>(Wi, Wf, Wg, Wo, Wci, Wcf, Wcg, Wco);
    k_conv_Wlin<<<(HD * 32 + 255) / 256, 256>>>(Wlin);
    k_count<<<(NE + 255) / 256, 256>>>(src, dst, ew);
    k_dinv<<<(NN + 255) / 256, 256>>>();
    k_scan<<<1, 1024>>>();
    k_fill<<<(NE + 255) / 256, 256>>>(src, dst, snid, dnid, ew);

    // gather + pack A directly
    k_gatherA<<<(NN + 3) / 4, 256>>>(x, h);

    __half *Ah, *Al, *Wp, *Rh, *Rl, *WlT;
    float *Zp;
    cudaGetSymbolAddress((void**)&Ah, g_Ah);
    cudaGetSymbolAddress((void**)&Al, g_Al);
    cudaGetSymbolAddress((void**)&Wp, g_W);
    cudaGetSymbolAddress((void**)&Zp, g_Z);
    cudaGetSymbolAddress((void**)&Rh, g_Rh);
    cudaGetSymbolAddress((void**)&Rl, g_Rl);
    cudaGetSymbolAddress((void**)&WlT, g_WlT);

    // big GEMM: Z[MPAD x 1024] = (Ah+Al) @ W^T   (2-product fp16, 128x256 CTA tile, K-tile 64)
    {
        dim3 grid(NCOL / 256, MPAD / 128);
        k_mma<<<grid, NTHR, SMEM_GEMM>>>(Ah, Al, Wp, Zp, KTOT, NCOL, nullptr, MPAD);
    }

    k_gates<<<(MPAD * 64 + 255) / 256, 256>>>(c, bci, bcf, bcg, bco, bi, bf, bg, bo,
                                              wci, wcf, wco, out);

    // small GEMM: h_out[NN x 256] = relu(h0) @ W_lin + b_lin   (2-product fp16)
    {
        dim3 grid(HD / 256, MPAD / 128);
        k_mma<<<grid, NTHR, SMEM_GEMM>>>(Rh, Rl, WlT, out, HD, HD, blin, NN);
    }
}

// round 17
// speedup vs baseline: 1.0850x; 1.0850x over previous
#include <cuda_runtime.h>
#include <cuda_fp16.h>
#include <math.h>
#include <stdint.h>

// Problem constants
#define NN    30000
#define NE    480000
#define HD    256
#define MPAD  30080      // 235*128
#define KTOT  768        // x_aug | h | t1
#define NCOL  1024       // 4 gates * 256 (gate-blocked: col = g*256 + j)
#define NH    (NN * HD)

// ---------------- static device scratch ----------------
__device__ float g_deg[NN];
__device__ int   g_cnt_src[NN], g_cnt_dst[NN];
__device__ int   g_off_src[NN], g_off_dst[NN];
__device__ int   g_cur_src[NN], g_cur_dst[NN];
__device__ int   g_nbr_src[NE];                   // resolved: snid[e] bucketed by src
__device__ int   g_nbr_dst[NE];                   // resolved: dnid[e] bucketed by dst
__device__ int   g_hsrc[NE];                      // resolved: src[e]  bucketed by dst
__device__ float g_nrm[NE];                       // resolved: norm_e  bucketed by dst
__device__ float g_Z[MPAD * NCOL];                // gate pre-activations (fp32)
__device__ __align__(16) __half g_Ah[MPAD * KTOT];   // A hi (fp16); pad rows stay 0
__device__ __align__(16) __half g_Al[MPAD * KTOT];   // A lo (fp16)
__device__ __align__(16) __half g_W [NCOL * KTOT];   // W transposed [n][k], single fp16
__device__ __align__(16) __half g_Rh[MPAD * HD];     // relu(h0) hi
__device__ __align__(16) __half g_Rl[MPAD * HD];     // relu(h0) lo
__device__ __align__(16) __half g_WlT[HD * HD];      // W_lin transposed, single fp16

__device__ __forceinline__ float sigf(float x) { return 1.0f / (1.0f + __expf(-x)); }
__device__ __forceinline__ float tanhfast(float x) {
    return 2.0f / (1.0f + __expf(-2.0f * x)) - 1.0f;
}

__device__ __forceinline__ uint32_t smem_u32(const void* p) {
    uint32_t a;
    asm("{ .reg .u64 t; cvta.to.shared.u64 t, %1; cvt.u32.u64 %0, t; }" : "=r"(a) : "l"(p));
    return a;
}

// ---------------- CSR build ----------------
__global__ __launch_bounds__(256) void k_zero() {
    int i = blockIdx.x * blockDim.x + threadIdx.x;
    if (i < NN) { g_cnt_src[i] = 0; g_cnt_dst[i] = 0; g_deg[i] = 0.f; }
}

__global__ __launch_bounds__(256) void k_count(const int* __restrict__ src,
                                               const int* __restrict__ dst,
                                               const float* __restrict__ ew) {
    int e = blockIdx.x * blockDim.x + threadIdx.x;
    if (e < NE) {
        int s = src[e], d = dst[e];
        atomicAdd(&g_cnt_src[s], 1);
        atomicAdd(&g_cnt_dst[d], 1);
        atomicAdd(&g_deg[s], ew[e]);
    }
}

__global__ __launch_bounds__(256) void k_dinv() {
    int i = blockIdx.x * blockDim.x + threadIdx.x;
    if (i < NN) {
        float d = g_deg[i];
        g_deg[i] = (d > 0.f) ? rsqrtf(fmaxf(d, 1e-12f)) : 0.f;
    }
}

// Exclusive scan of both count arrays -> offsets + cursors.
// One block per pass (blockIdx.x = 0: src, 1: dst) — the two passes are independent.
#define SCH 30   // 1024*30 = 30720 >= NN
__global__ __launch_bounds__(1024) void k_scan() {
    __shared__ int sh[1024];
    int t = threadIdx.x;
    int base = t * SCH;
    int pass = blockIdx.x;
    const int* cnt = pass ? g_cnt_dst : g_cnt_src;
    int* off = pass ? g_off_dst : g_off_src;
    int* cur = pass ? g_cur_dst : g_cur_src;
    int local = 0;
    for (int i = 0; i < SCH; i++) {
        int idx = base + i;
        if (idx < NN) local += cnt[idx];
    }
    sh[t] = local;
    __syncthreads();
    for (int o = 1; o < 1024; o <<= 1) {
        int v = 0;
        if (t >= o) v = sh[t - o];
        __syncthreads();
        if (t >= o) sh[t] += v;
        __syncthreads();
    }
    int run = (t > 0) ? sh[t - 1] : 0;
    for (int i = 0; i < SCH; i++) {
        int idx = base + i;
        if (idx < NN) {
            off[idx] = run;
            cur[idx] = run;
            run += cnt[idx];
        }
    }
}

__global__ __launch_bounds__(256) void k_fill(const int* __restrict__ src,
                                              const int* __restrict__ dst,
                                              const int* __restrict__ snid,
                                              const int* __restrict__ dnid,
                                              const float* __restrict__ ew) {
    int e = blockIdx.x * blockDim.x + threadIdx.x;
    if (e < NE) {
        int s = src[e], d = dst[e];
        int ps = atomicAdd(&g_cur_src[s], 1);
        g_nbr_src[ps] = snid[e];
        int pd = atomicAdd(&g_cur_dst[d], 1);
        g_nbr_dst[pd] = dnid[e];
        g_hsrc[pd] = s;
        g_nrm[pd] = -g_deg[s] * ew[e] * g_deg[d];
    }
}

// ---------------- fp32 -> fp16 hi/lo split ----------------
__device__ __forceinline__ void split4h(float4 v, uint2& hi, uint2& lo) {
    __half h[4], l[4];
    float f[4] = {v.x, v.y, v.z, v.w};
#pragma unroll
    for (int t = 0; t < 4; t++) {
        h[t] = __float2half(f[t]);
        l[t] = __float2half(f[t] - __half2float(h[t]));
    }
    hi = *reinterpret_cast<uint2*>(h);
    lo = *reinterpret_cast<uint2*>(l);
}

// ---------------- gather + pack A (fp16 split), plain broadcast-index form ----
__global__ __launch_bounds__(256) void k_gatherA(
    const float* __restrict__ x, const float* __restrict__ h)
{
    int node = blockIdx.x * 4 + (threadIdx.x >> 6);
    int t = threadIdx.x & 63;
    if (node >= NN) return;

    const float4* x4 = reinterpret_cast<const float4*>(x);
    const float4* h4 = reinterpret_cast<const float4*>(h);

    float4 ax = x4[(size_t)node * 64 + t];
    float4 at = make_float4(0.f, 0.f, 0.f, 0.f);

    {
        int o = g_off_src[node], c = g_cnt_src[node];
#pragma unroll 4
        for (int i = 0; i < c; i++) {
            int sn = g_nbr_src[o + i];
            float4 v = x4[(size_t)sn * 64 + t];
            ax.x += v.x; ax.y += v.y; ax.z += v.z; ax.w += v.w;
        }
    }
    {
        int o = g_off_dst[node], c = g_cnt_dst[node];
#pragma unroll 4
        for (int i = 0; i < c; i++) {
            int dn = g_nbr_dst[o + i];
            int s  = g_hsrc[o + i];
            float nm = g_nrm[o + i];
            float4 v = x4[(size_t)dn * 64 + t];
            ax.x += v.x; ax.y += v.y; ax.z += v.z; ax.w += v.w;
            float4 hv = h4[(size_t)s * 64 + t];
            at.x += nm * hv.x; at.y += nm * hv.y; at.z += nm * hv.z; at.w += nm * hv.w;
        }
    }

    float4 hr = h4[(size_t)node * 64 + t];

    uint2 hi, lo;
    size_t rb = (size_t)node * KTOT;
    split4h(ax, hi, lo);
    *reinterpret_cast<uint2*>(g_Ah + rb + t * 4) = hi;
    *reinterpret_cast<uint2*>(g_Al + rb + t * 4) = lo;
    split4h(hr, hi, lo);
    *reinterpret_cast<uint2*>(g_Ah + rb + 256 + t * 4) = hi;
    *reinterpret_cast<uint2*>(g_Al + rb + 256 + t * 4) = lo;
    split4h(at, hi, lo);
    *reinterpret_cast<uint2*>(g_Ah + rb + 512 + t * 4) = hi;
    *reinterpret_cast<uint2*>(g_Al + rb + 512 + t * 4) = lo;
}

// ---------------- weight packs (single fp16) ----------------
__global__ __launch_bounds__(256) void k_conv_W(
    const float* __restrict__ Wi, const float* __restrict__ Wf,
    const float* __restrict__ Wg, const float* __restrict__ Wo,
    const float* __restrict__ Wci, const float* __restrict__ Wcf,
    const float* __restrict__ Wcg, const float* __restrict__ Wco)
{
    int i = blockIdx.x * blockDim.x + threadIdx.x;   // over NCOL*96
    if (i >= NCOL * 96) return;
    int n = i / 96;
    int kc = i % 96;
    int g = n >> 8, j = n & 255;
    const float* Win[4] = {Wi, Wf, Wg, Wo};
    const float* Wc[4]  = {Wci, Wcf, Wcg, Wco};
    __half v[8];
#pragma unroll
    for (int t = 0; t < 8; t++) {
        int k = kc * 8 + t;
        float f;
        if (k < 256)      f = Win[g][k * 256 + j];
        else if (k < 512) f = Wc[g][(k - 256) * 256 + j];
        else              f = Wc[g][65536 + (k - 512) * 256 + j];
        v[t] = __float2half(f);
    }
    reinterpret_cast<uint4*>(g_W)[i] = *reinterpret_cast<uint4*>(v);
}

__global__ __launch_bounds__(256) void k_conv_Wlin(const float* __restrict__ Wlin) {
    int i = blockIdx.x * blockDim.x + threadIdx.x;   // over 256*32
    if (i >= HD * 32) return;
    int n = i / 32;
    int kc = i % 32;
    __half v[8];
#pragma unroll
    for (int t = 0; t < 8; t++) v[t] = __float2half(Wlin[(kc * 8 + t) * 256 + n]);
    reinterpret_cast<uint4*>(g_WlT)[i] = *reinterpret_cast<uint4*>(v);
}

// ============ fp16 2-product GEMM via mma.sync ============
// C = (Ah + Al)[M x K] @ B^T, B stored [Ncols x K] row-major fp16.
// CTA tile 128x256, 512 threads (16 warps, 2x8), warp tile 64x32,
// K-tile 64, 2-stage cp.async pipeline with issue-before-compute.
#define BKG   64
#define NSTG  2
#define TSTR  144                   // 128B payload + 16B pad; 8-row shifts distinct -> conflict-free
#define A_TILEB (128 * TSTR)        // 18432 B (per A operand)
#define B_TILEB (256 * TSTR)        // 36864 B
#define STAGEB  (2 * A_TILEB + B_TILEB)   // 73728 B
#define SMEM_GEMM (NSTG * STAGEB)   // 147456 B
#define NTHR  512

__device__ __forceinline__ void cp16(uint32_t saddr, const void* gaddr) {
    asm volatile("cp.async.cg.shared.global [%0], [%1], 16;" :: "r"(saddr), "l"(gaddr));
}
__device__ __forceinline__ void ldm_x4(uint32_t* r, uint32_t a) {
    asm volatile("ldmatrix.sync.aligned.m8n8.x4.shared.b16 {%0,%1,%2,%3}, [%4];"
                 : "=r"(r[0]), "=r"(r[1]), "=r"(r[2]), "=r"(r[3]) : "r"(a));
}
__device__ __forceinline__ void ldm_x2(uint32_t* r, uint32_t a) {
    asm volatile("ldmatrix.sync.aligned.m8n8.x2.shared.b16 {%0,%1}, [%2];"
                 : "=r"(r[0]), "=r"(r[1]) : "r"(a));
}
__device__ __forceinline__ void mma16816h(float* c, const uint32_t* a, const uint32_t* b) {
    asm volatile(
        "mma.sync.aligned.m16n8k16.row.col.f32.f16.f16.f32 "
        "{%0,%1,%2,%3}, {%4,%5,%6,%7}, {%8,%9}, {%0,%1,%2,%3};"
        : "+f"(c[0]), "+f"(c[1]), "+f"(c[2]), "+f"(c[3])
        : "r"(a[0]), "r"(a[1]), "r"(a[2]), "r"(a[3]), "r"(b[0]), "r"(b[1]));
}

__global__ __launch_bounds__(NTHR) void k_mma(
    const __half* __restrict__ Ah, const __half* __restrict__ Al,
    const __half* __restrict__ B,
    float* __restrict__ C, int K, int Ncols, const float* __restrict__ bias, int m_limit)
{
    extern __shared__ char smem[];
    const int tid = threadIdx.x;
    const int wid = tid >> 5;
    const int lane = tid & 31;
    const int m0 = blockIdx.y * 128;
    const int n0 = blockIdx.x * 256;
    const int nkt = K / BKG;
    const uint32_t sb = smem_u32(smem);

    const int wr = (wid >> 3) * 64;    // 2 row-groups of warps
    const int wc = (wid & 7) * 32;     // 8 col-groups

    // cp.async chunk coords: rows of 128B payload = 8 chunks of 16B per row.
    const int r0 = tid >> 3;           // 0..63
    const int c0 = (tid & 7) * 16;     // byte column within 128B payload

    float acc[4][4][4] = {};

    auto issue_stage = [&](int kt, int buf) {
        uint32_t s = sb + buf * STAGEB;
        const char* ahB = reinterpret_cast<const char*>(Ah);
        const char* alB = reinterpret_cast<const char*>(Al);
        const char* bB  = reinterpret_cast<const char*>(B);
        size_t kb = (size_t)kt * BKG * 2;   // 128 bytes per k-tile
#pragma unroll
        for (int rep = 0; rep < 2; rep++) {         // A rows 0..127
            int row = r0 + rep * 64;
            size_t ga = ((size_t)(m0 + row) * K) * 2 + kb + c0;
            uint32_t so = row * TSTR + c0;
            cp16(s + so, ahB + ga);
            cp16(s + A_TILEB + so, alB + ga);
        }
#pragma unroll
        for (int rep = 0; rep < 4; rep++) {         // B rows 0..255
            int row = r0 + rep * 64;
            size_t gb = ((size_t)(n0 + row) * K) * 2 + kb + c0;
            uint32_t so = row * TSTR + c0;
            cp16(s + 2 * A_TILEB + so, bB + gb);
        }
    };

    // prologue: fill stage 0
    issue_stage(0, 0);
    asm volatile("cp.async.commit_group;");

    for (int kt = 0; kt < nkt; kt++) {
        asm volatile("cp.async.wait_group 0;");
        __syncthreads();                       // all warps done with the buffer we're about to overwrite

        // overlap: issue next stage before computing current
        if (kt + 1 < nkt) issue_stage(kt + 1, (kt + 1) & 1);
        asm volatile("cp.async.commit_group;");

        uint32_t s = sb + (kt & 1) * STAGEB;
        uint32_t sAh = s, sAl = s + A_TILEB, sB = s + 2 * A_TILEB;

#pragma unroll
        for (int ks = 0; ks < 4; ks++) {
            uint32_t ah[4][4], al[4][4], bh[4][2];
            uint32_t aoff = (wr + (lane & 15)) * TSTR + ks * 32 + ((lane >> 4) & 1) * 16;
#pragma unroll
            for (int mt = 0; mt < 4; mt++) {
                ldm_x4(ah[mt], sAh + aoff + mt * 16 * TSTR);
                ldm_x4(al[mt], sAl + aoff + mt * 16 * TSTR);
            }
            int l = lane & 15;
            uint32_t boff = (wc + (l & 7)) * TSTR + ks * 32 + ((l >> 3) & 1) * 16;
#pragma unroll
            for (int nt = 0; nt < 4; nt++) {
                ldm_x2(bh[nt], sB + boff + nt * 8 * TSTR);
            }
#pragma unroll
            for (int mt = 0; mt < 4; mt++)
#pragma unroll
                for (int nt = 0; nt < 4; nt++) {
                    mma16816h(acc[mt][nt], ah[mt], bh[nt]);
                    mma16816h(acc[mt][nt], al[mt], bh[nt]);
                }
        }
    }

#pragma unroll
    for (int mt = 0; mt < 4; mt++) {
        int rAo = m0 + wr + mt * 16 + (lane >> 2);
        int rBo = rAo + 8;
#pragma unroll
        for (int nt = 0; nt < 4; nt++) {
            int col = n0 + wc + nt * 8 + (lane & 3) * 2;
            float bx = 0.f, by = 0.f;
            if (bias) { bx = bias[col]; by = bias[col + 1]; }
            if (rAo < m_limit) {
                float2 v = make_float2(acc[mt][nt][0] + bx, acc[mt][nt][1] + by);
                *reinterpret_cast<float2*>(C + (size_t)rAo * Ncols + col) = v;
            }
            if (rBo < m_limit) {
                float2 v = make_float2(acc[mt][nt][2] + bx, acc[mt][nt][3] + by);
                *reinterpret_cast<float2*>(C + (size_t)rBo * Ncols + col) = v;
            }
        }
    }
}

// ---------------- gates: vectorized x4 — h0, c_new, relu split (fp16) ----------------
__global__ __launch_bounds__(256) void k_gates(
    const float* __restrict__ c,
    const float* __restrict__ bci, const float* __restrict__ bcf,
    const float* __restrict__ bcg, const float* __restrict__ bco,
    const float* __restrict__ bi, const float* __restrict__ bf,
    const float* __restrict__ bg, const float* __restrict__ bo,
    const float* __restrict__ wci, const float* __restrict__ wcf,
    const float* __restrict__ wco,
    float* __restrict__ out)
{
    int i = blockIdx.x * blockDim.x + threadIdx.x;   // over MPAD*64 float4 groups
    if (i >= MPAD * 64) return;
    int row = i >> 6;
    int q = i & 63;
    int j = q * 4;
    size_t off = (size_t)row * HD + j;

    if (row >= NN) {
        uint2 z2 = make_uint2(0u, 0u);
        *reinterpret_cast<uint2*>(g_Rh + off) = z2;
        *reinterpret_cast<uint2*>(g_Rl + off) = z2;
        return;
    }

    const float* zrow = g_Z + (size_t)row * NCOL;
    float4 zi4 = *reinterpret_cast<const float4*>(zrow + j);
    float4 zf4 = *reinterpret_cast<const float4*>(zrow + 256 + j);
    float4 zg4 = *reinterpret_cast<const float4*>(zrow + 512 + j);
    float4 zo4 = *reinterpret_cast<const float4*>(zrow + 768 + j);
    float4 cv4 = *reinterpret_cast<const float4*>(c + off);
    float4 wI = *reinterpret_cast<const float4*>(wci + j);
    float4 wF = *reinterpret_cast<const float4*>(wcf + j);
    float4 wO = *reinterpret_cast<const float4*>(wco + j);

    float zi[4] = {zi4.x, zi4.y, zi4.z, zi4.w};
    float zf[4] = {zf4.x, zf4.y, zf4.z, zf4.w};
    float zg[4] = {zg4.x, zg4.y, zg4.z, zg4.w};
    float zo[4] = {zo4.x, zo4.y, zo4.z, zo4.w};
    float cv[4] = {cv4.x, cv4.y, cv4.z, cv4.w};
    float pI[4] = {wI.x, wI.y, wI.z, wI.w};
    float pF[4] = {wF.x, wF.y, wF.z, wF.w};
    float pO[4] = {wO.x, wO.y, wO.z, wO.w};

    float h0v[4], cnv[4];
    __half rh[4], rl[4];
#pragma unroll
    for (int t = 0; t < 4; t++) {
        float ig = sigf(zi[t] + bci[j + t] + bi[j + t] + pI[t] * cv[t]);
        float fg = sigf(zf[t] + bcf[j + t] + bf[j + t] + pF[t] * cv[t]);
        float gg = tanhfast(zg[t] + bcg[j + t] + bg[j + t]);
        float cn = fg * cv[t] + ig * gg;
        float og = sigf(zo[t] + bco[j + t] + bo[j + t] + pO[t] * cn);
        float h0 = og * tanhfast(cn);
        h0v[t] = h0;
        cnv[t] = cn;
        float r = fmaxf(h0, 0.f);
        rh[t] = __float2half(r);
        rl[t] = __float2half(r - __half2float(rh[t]));
    }
    *reinterpret_cast<float4*>(out + NH + off) = make_float4(h0v[0], h0v[1], h0v[2], h0v[3]);
    *reinterpret_cast<float4*>(out + 2 * NH + off) = make_float4(cnv[0], cnv[1], cnv[2], cnv[3]);
    *reinterpret_cast<uint2*>(g_Rh + off) = *reinterpret_cast<uint2*>(rh);
    *reinterpret_cast<uint2*>(g_Rl + off) = *reinterpret_cast<uint2*>(rl);
}

// ---------------- launch ----------------
extern "C" void kernel_launch(void* const* d_in, const int* in_sizes, int n_in,
                              void* d_out, int out_size) {
    const float* x    = (const float*)d_in[0];
    const int*   ei   = (const int*)d_in[1];
    const float* ew   = (const float*)d_in[2];
    const float* h    = (const float*)d_in[3];
    const float* c    = (const float*)d_in[4];
    const int*   snid = (const int*)d_in[5];
    const int*   dnid = (const int*)d_in[6];
    const float* Wi   = (const float*)d_in[7];
    const float* Wf   = (const float*)d_in[8];
    const float* Wg   = (const float*)d_in[9];
    const float* Wo   = (const float*)d_in[10];
    const float* Wci  = (const float*)d_in[11];
    const float* Wcf  = (const float*)d_in[12];
    const float* Wcg  = (const float*)d_in[13];
    const float* Wco  = (const float*)d_in[14];
    const float* bci  = (const float*)d_in[15];
    const float* bcf  = (const float*)d_in[16];
    const float* bcg  = (const float*)d_in[17];
    const float* bco  = (const float*)d_in[18];

    const float *bi, *bf, *bg, *bo, *blin, *wci, *wcf, *wco, *Wlin;
    if (in_sizes[27] == 65536) {
        bi = (const float*)d_in[19]; bf = (const float*)d_in[20];
        bg = (const float*)d_in[21]; bo = (const float*)d_in[22];
        blin = (const float*)d_in[23];
        wci = (const float*)d_in[24]; wcf = (const float*)d_in[25];
        wco = (const float*)d_in[26];
        Wlin = (const float*)d_in[27];
    } else {
        wci = (const float*)d_in[19]; wcf = (const float*)d_in[20];
        wco = (const float*)d_in[21];
        bi = (const float*)d_in[22]; bf = (const float*)d_in[23];
        bg = (const float*)d_in[24]; bo = (const float*)d_in[25];
        Wlin = (const float*)d_in[26];
        blin = (const float*)d_in[27];
    }

    const int* src = ei;
    const int* dst = ei + NE;
    float* out = (float*)d_out;

    cudaFuncSetAttribute(k_mma, cudaFuncAttributeMaxDynamicSharedMemorySize, SMEM_GEMM);

    // CSR build (field-resolving) + weight packs
    k_zero<<<(NN + 255) / 256, 256>>>();
    k_conv_W<<<(NCOL * 96 + 255) / 256, 256>>>(Wi, Wf, Wg, Wo, Wci, Wcf, Wcg, Wco);
    k_conv_Wlin<<<(HD * 32 + 255) / 256, 256>>>(Wlin);
    k_count<<<(NE + 255) / 256, 256>>>(src, dst, ew);
    k_dinv<<<(NN + 255) / 256, 256>>>();
    k_scan<<<2, 1024>>>();
    k_fill<<<(NE + 255) / 256, 256>>>(src, dst, snid, dnid, ew);

    // gather + pack A directly
    k_gatherA<<<(NN + 3) / 4, 256>>>(x, h);

    __half *Ah, *Al, *Wp, *Rh, *Rl, *WlT;
    float *Zp;
    cudaGetSymbolAddress((void**)&Ah, g_Ah);
    cudaGetSymbolAddress((void**)&Al, g_Al);
    cudaGetSymbolAddress((void**)&Wp, g_W);
    cudaGetSymbolAddress((void**)&Zp, g_Z);
    cudaGetSymbolAddress((void**)&Rh, g_Rh);
    cudaGetSymbolAddress((void**)&Rl, g_Rl);
    cudaGetSymbolAddress((void**)&WlT, g_WlT);

    // big GEMM: Z[MPAD x 1024] = (Ah+Al) @ W^T   (2-product fp16, 128x256 CTA tile, K-tile 64)
    {
        dim3 grid(NCOL / 256, MPAD / 128);
        k_mma<<<grid, NTHR, SMEM_GEMM>>>(Ah, Al, Wp, Zp, KTOT, NCOL, nullptr, MPAD);
    }

    k_gates<<<(MPAD * 64 + 255) / 256, 256>>>(c, bci, bcf, bcg, bco, bi, bf, bg, bo,
                                              wci, wcf, wco, out);

    // small GEMM: h_out[NN x 256] = relu(h0) @ W_lin + b_lin   (2-product fp16)
    {
        dim3 grid(HD / 256, MPAD / 128);
        k_mma<<<grid, NTHR, SMEM_GEMM>>>(Rh, Rl, WlT, out, HD, HD, blin, NN);
    }
}